// round 13
// baseline (speedup 1.0000x reference)
#include <cuda_runtime.h>
#include <cuda_bf16.h>
#include <cuda_fp16.h>
#include <math.h>
#include <stdint.h>

#define BATCH 2
#define HEADS 16
#define SEQ   2048
#define DIM   64
#define BH    (BATCH*HEADS)
#define BM    128
#define BN    64
#define NT    (SEQ/BN)          // 32 kv tiles per bh

// per-tile fragment-ordered global layouts
#define KT_U32 4096             // K tile: 32 blocks x 32 lanes x 16B = 16384 B
#define VT_U32 2048             // V tile: 32 blocks x 32 lanes x 8B  =  8192 B
#define KT_BYTES 16384
#define VT_BYTES 8192
#define STAGE_BYTES (KT_BYTES + VT_BYTES)   // 24576
#define SM_TOTAL (4 * STAGE_BYTES)          // 98304 (4-stage ring)

__device__ __align__(16) float    g_Qr[BH*SEQ*DIM];
__device__ __align__(16) uint32_t g_Kf[BH*NT*KT_U32];
__device__ __align__(16) uint32_t g_Vf[BH*NT*VT_U32];

// ---------------------------------------------------------------------------
__device__ __forceinline__ void bsplit2(float f0, float f1, uint32_t& hi, uint32_t& lo) {
    __nv_bfloat16 h0 = __float2bfloat16_rn(f0);
    __nv_bfloat16 h1 = __float2bfloat16_rn(f1);
    float r0 = f0 - __bfloat162float(h0);
    float r1 = f1 - __bfloat162float(h1);
    __nv_bfloat162 H = {h0, h1};
    __nv_bfloat162 L = {__float2bfloat16_rn(r0), __float2bfloat16_rn(r1)};
    hi = *(uint32_t*)&H;
    lo = *(uint32_t*)&L;
}
__device__ __forceinline__ float ex2f(float x) {
    float r; asm("ex2.approx.f32 %0, %1;" : "=f"(r) : "f"(x)); return r;
}
__device__ __forceinline__ void mma16(float* c, const uint32_t* a, uint32_t b0, uint32_t b1) {
    asm volatile("mma.sync.aligned.m16n8k16.row.col.f32.bf16.bf16.f32 "
        "{%0,%1,%2,%3}, {%4,%5,%6,%7}, {%8,%9}, {%0,%1,%2,%3};"
        : "+f"(c[0]), "+f"(c[1]), "+f"(c[2]), "+f"(c[3])
        : "r"(a[0]), "r"(a[1]), "r"(a[2]), "r"(a[3]), "r"(b0), "r"(b1));
}
__device__ __forceinline__ void mma16f(float* c, const uint32_t* a, uint32_t b0, uint32_t b1) {
    asm volatile("mma.sync.aligned.m16n8k16.row.col.f32.f16.f16.f32 "
        "{%0,%1,%2,%3}, {%4,%5,%6,%7}, {%8,%9}, {%0,%1,%2,%3};"
        : "+f"(c[0]), "+f"(c[1]), "+f"(c[2]), "+f"(c[3])
        : "r"(a[0]), "r"(a[1]), "r"(a[2]), "r"(a[3]), "r"(b0), "r"(b1));
}
__device__ __forceinline__ uint32_t smem_u32(const void* p) {
    uint32_t a;
    asm("{ .reg .u64 t; cvta.to.shared.u64 t, %1; cvt.u32.u64 %0, t; }" : "=r"(a) : "l"(p));
    return a;
}
__device__ __forceinline__ void cp16(uint32_t saddr, const void* g) {
    asm volatile("cp.async.cg.shared.global [%0], [%1], 16;" :: "r"(saddr), "l"(g));
}
#define CP_COMMIT() asm volatile("cp.async.commit_group;" ::: "memory")
#define CP_WAIT(n)  asm volatile("cp.async.wait_group %0;" :: "n"(n) : "memory")

// ---------------------------------------------------------------------------
// Fused prep: [0,N1): Q -> g_Qr, K -> (RoPE*log2e) bf16 hi/lo fragments
//             [N1,N1+N2): V -> f16x2 fragments
// ---------------------------------------------------------------------------
#define N1 (BH*SEQ*32)
#define N2 (BH*NT*32*64)

__global__ void prep_kernel(const float* __restrict__ Q, const float* __restrict__ K,
                            const float* __restrict__ V) {
    int idx = blockIdx.x * blockDim.x + threadIdx.x;
    if (idx < N1) {
        int i   = idx & 31;           // pair index 0..31
        int row = idx >> 5;
        int s   = row & (SEQ - 1);
        int bh  = row >> 11;
        float div = expf((float)(2 * i) * (-9.210340371976184f / 64.0f));
        float sv, cv; sincosf((float)s * div, &sv, &cv);
        int base = row * DIM + 2 * i;
        float qe = Q[base], qo = Q[base + 1];
        g_Qr[base]     = qe * cv - qo * sv;
        g_Qr[base + 1] = qe * sv + qo * cv;

        const float L2E = 1.4426950408889634f;   // scores in log2 domain
        float ke = K[base], ko = K[base + 1];
        float k0 = (ke * cv - ko * sv) * L2E;
        float k1 = (ke * sv + ko * cv) * L2E;
        uint32_t hi, lo; bsplit2(k0, k1, hi, lo);
        int tile = s >> 6;
        int j = (s >> 3) & 7, g = s & 7;
        int kc = i >> 3, pp = i & 7, c0 = pp & 3, hq = pp >> 2;
        uint32_t* kb = g_Kf + (size_t)(bh * NT + tile) * KT_U32
                     + (j * 4 + kc) * 128 + (g * 4 + c0) * 4 + hq;
        kb[0] = hi;
        kb[2] = lo;
    } else if (idx < N1 + N2) {
        int vi   = idx - N1;
        int n    = vi & 63;
        int rp   = (vi >> 6) & 31;
        int tile = (vi >> 11) & 31;
        int bh   = vi >> 16;
        const float* vb = V + ((size_t)bh * SEQ + tile * 64) * DIM;
        __half2 h = __floats2half2_rn(vb[(2 * rp) * DIM + n], vb[(2 * rp + 1) * DIM + n]);
        int kc = rp >> 3, ctg = rp & 3, slot = (rp & 4) ? 1 : 0;
        int jd = n >> 3, gid = n & 7;
        g_Vf[(size_t)(bh * NT + tile) * VT_U32
             + (kc * 8 + jd) * 64 + (gid * 4 + ctg) * 2 + slot] = *(uint32_t*)&h;
    }
}

// ---------------------------------------------------------------------------
__global__ __launch_bounds__(256, 1) void flash_kernel(float* __restrict__ Og) {
    extern __shared__ __align__(16) char dsm[];
    const uint32_t sbase = smem_u32(dsm);

    const int tid  = threadIdx.x;
    const int w    = tid >> 5;
    const int lane = tid & 31;
    const int gid  = lane >> 2;
    const int ctg  = lane & 3;

    const int bh = blockIdx.y;
    const int q0 = ((int)(gridDim.x - 1) - (int)blockIdx.x) * BM;   // heavy tiles first
    const float* Qg = g_Qr + ((size_t)bh * SEQ + q0 + w * 16) * DIM;
    const uint32_t* Kt = g_Kf + (size_t)bh * NT * KT_U32;
    const uint32_t* Vt = g_Vf + (size_t)bh * NT * VT_U32;

    // ---- persistent Q A-fragments, bf16 hi/lo: 32 regs ----
    uint32_t qh[4][4], ql[4][4];
    #pragma unroll
    for (int kc = 0; kc < 4; kc++) {
        const int e0 = 16 * kc + 2 * ctg;
        bsplit2(Qg[gid * DIM + e0],           Qg[gid * DIM + e0 + 1],       qh[kc][0], ql[kc][0]);
        bsplit2(Qg[(gid + 8) * DIM + e0],     Qg[(gid + 8) * DIM + e0 + 1], qh[kc][1], ql[kc][1]);
        bsplit2(Qg[gid * DIM + e0 + 8],       Qg[gid * DIM + e0 + 9],       qh[kc][2], ql[kc][2]);
        bsplit2(Qg[(gid + 8) * DIM + e0 + 8], Qg[(gid + 8) * DIM + e0 + 9], qh[kc][3], ql[kc][3]);
    }

    float o[8][4];
    #pragma unroll
    for (int j = 0; j < 8; j++) { o[j][0] = o[j][1] = o[j][2] = o[j][3] = 0.f; }
    float m0 = -INFINITY, m1 = -INFINITY, l0 = 0.f, l1 = 0.f;
    const int r0g = q0 + w * 16 + gid;
    const int r1g = r0g + 8;

    const int ntiles = q0 / BN + 2;

    // async copy of tile t into ring stage t%4 (contiguous, fragment-ordered)
    auto issue = [&](int t) {
        uint32_t dst = sbase + (uint32_t)(t & 3) * STAGE_BYTES;
        const char* gk = (const char*)(Kt + (size_t)t * KT_U32);
        const char* gv = (const char*)(Vt + (size_t)t * VT_U32);
        #pragma unroll
        for (int it = 0; it < 4; it++)
            cp16(dst + (tid + it * 256) * 16, gk + (tid + it * 256) * 16);
        #pragma unroll
        for (int it = 0; it < 2; it++)
            cp16(dst + KT_BYTES + (tid + it * 256) * 16, gv + (tid + it * 256) * 16);
    };
    // GEMM1 for tile data in buf -> sacc (3x bf16 m16n8k16)
    float sacc[8][4];
    auto gemm1 = [&](const char* buf) {
        #pragma unroll
        for (int j = 0; j < 8; j++)
            sacc[j][0] = sacc[j][1] = sacc[j][2] = sacc[j][3] = 0.f;
        #pragma unroll
        for (int kc = 0; kc < 4; kc++) {
            #pragma unroll
            for (int j = 0; j < 8; j++) {
                float4 fr = *(const float4*)(buf + (j * 4 + kc) * 512 + lane * 16);
                uint32_t bh0 = __float_as_uint(fr.x), bh1 = __float_as_uint(fr.y);
                uint32_t bl0 = __float_as_uint(fr.z), bl1 = __float_as_uint(fr.w);
                mma16(sacc[j], qh[kc], bh0, bh1);
                mma16(sacc[j], ql[kc], bh0, bh1);
                mma16(sacc[j], qh[kc], bl0, bl1);
            }
        }
    };

    // prologue: prefetch tiles 0..2 (tile indices < NT always; extra data unused)
    issue(0); CP_COMMIT();
    issue(1); CP_COMMIT();
    issue(2); CP_COMMIT();
    CP_WAIT(2);                 // stage 0 landed
    __syncthreads();
    gemm1(dsm);                 // GEMM1(0)

    for (int t = 0; t < ntiles; t++) {
        const int kv0 = t * BN;
        const char* bufC = dsm + (t & 3) * STAGE_BYTES;

        // ---- causal mask (warp-uniform skip) + online softmax (log2 domain) ----
        if (kv0 + BN - 1 > q0 + w * 16) {
            #pragma unroll
            for (int j = 0; j < 8; j++) {
                const int c0 = kv0 + 8 * j + 2 * ctg, c1 = c0 + 1;
                if (c0 > r0g) sacc[j][0] = -INFINITY;
                if (c1 > r0g) sacc[j][1] = -INFINITY;
                if (c0 > r1g) sacc[j][2] = -INFINITY;
                if (c1 > r1g) sacc[j][3] = -INFINITY;
            }
        }
        float mx0 = -INFINITY, mx1 = -INFINITY;
        #pragma unroll
        for (int j = 0; j < 8; j++) {
            mx0 = fmaxf(mx0, fmaxf(sacc[j][0], sacc[j][1]));
            mx1 = fmaxf(mx1, fmaxf(sacc[j][2], sacc[j][3]));
        }
        mx0 = fmaxf(mx0, __shfl_xor_sync(0xffffffffu, mx0, 1));
        mx0 = fmaxf(mx0, __shfl_xor_sync(0xffffffffu, mx0, 2));
        mx1 = fmaxf(mx1, __shfl_xor_sync(0xffffffffu, mx1, 1));
        mx1 = fmaxf(mx1, __shfl_xor_sync(0xffffffffu, mx1, 2));

        const float mn0 = fmaxf(m0, mx0), mn1 = fmaxf(m1, mx1);
        const float a0s = ex2f(m0 - mn0), a1s = ex2f(m1 - mn1);
        float s0 = 0.f, s1 = 0.f;
        #pragma unroll
        for (int j = 0; j < 8; j++) {
            float p0 = ex2f(sacc[j][0] - mn0), p1 = ex2f(sacc[j][1] - mn0);
            float p2 = ex2f(sacc[j][2] - mn1), p3 = ex2f(sacc[j][3] - mn1);
            sacc[j][0] = p0; sacc[j][1] = p1; sacc[j][2] = p2; sacc[j][3] = p3;
            s0 += p0 + p1; s1 += p2 + p3;
        }
        s0 += __shfl_xor_sync(0xffffffffu, s0, 1);
        s0 += __shfl_xor_sync(0xffffffffu, s0, 2);
        s1 += __shfl_xor_sync(0xffffffffu, s1, 1);
        s1 += __shfl_xor_sync(0xffffffffu, s1, 2);
        l0 = l0 * a0s + s0; m0 = mn0;
        l1 = l1 * a1s + s1; m1 = mn1;
        #pragma unroll
        for (int j = 0; j < 8; j++) {
            o[j][0] *= a0s; o[j][1] *= a0s; o[j][2] *= a1s; o[j][3] *= a1s;
        }

        // ---- pack P into f16 A-fragments (frees sacc for GEMM1(t+1)) ----
        uint32_t pa[4][4];
        #pragma unroll
        for (int kc = 0; kc < 4; kc++) {
            __half2 a0 = __floats2half2_rn(sacc[2*kc][0],   sacc[2*kc][1]);
            __half2 a1 = __floats2half2_rn(sacc[2*kc][2],   sacc[2*kc][3]);
            __half2 a2 = __floats2half2_rn(sacc[2*kc+1][0], sacc[2*kc+1][1]);
            __half2 a3 = __floats2half2_rn(sacc[2*kc+1][2], sacc[2*kc+1][3]);
            pa[kc][0] = *(uint32_t*)&a0; pa[kc][1] = *(uint32_t*)&a1;
            pa[kc][2] = *(uint32_t*)&a2; pa[kc][3] = *(uint32_t*)&a3;
        }

        if (t + 1 < ntiles) {
            CP_WAIT(1);                  // stage t+1 landed (this thread)
            __syncthreads();             // all threads landed; all done reading stage t-1
            if (t + 3 < ntiles) { issue(t + 3); CP_COMMIT(); }

            const char* bufN = dsm + ((t + 1) & 3) * STAGE_BYTES;
            // ---- interleaved: GEMM1(t+1) -> sacc  ⊕  GEMM2(t): O += P @ V ----
            #pragma unroll
            for (int kc = 0; kc < 4; kc++) {
                #pragma unroll
                for (int j = 0; j < 8; j++) {
                    float4 fr = *(const float4*)(bufN + (j * 4 + kc) * 512 + lane * 16);
                    uint32_t bh0 = __float_as_uint(fr.x), bh1 = __float_as_uint(fr.y);
                    uint32_t bl0 = __float_as_uint(fr.z), bl1 = __float_as_uint(fr.w);
                    float* cj = sacc[j];
                    if (kc == 0) { cj[0] = 0.f; cj[1] = 0.f; cj[2] = 0.f; cj[3] = 0.f; }
                    mma16(cj, qh[kc], bh0, bh1);
                    mma16(cj, ql[kc], bh0, bh1);
                    mma16(cj, qh[kc], bl0, bl1);
                }
                #pragma unroll
                for (int jd = 0; jd < 8; jd++) {
                    uint2 b = *(const uint2*)(bufC + KT_BYTES + (kc * 8 + jd) * 256 + lane * 8);
                    mma16f(o[jd], pa[kc], b.x, b.y);
                }
            }
        } else {
            // ---- last tile: GEMM2 only ----
            #pragma unroll
            for (int kc = 0; kc < 4; kc++) {
                #pragma unroll
                for (int jd = 0; jd < 8; jd++) {
                    uint2 b = *(const uint2*)(bufC + KT_BYTES + (kc * 8 + jd) * 256 + lane * 8);
                    mma16f(o[jd], pa[kc], b.x, b.y);
                }
            }
        }
    }

    // ---- epilogue ----
    const float i0 = 1.f / l0, i1 = 1.f / l1;
    float* out0 = Og + ((size_t)bh * SEQ + r0g) * DIM;
    float* out1 = Og + ((size_t)bh * SEQ + r1g) * DIM;
    #pragma unroll
    for (int jd = 0; jd < 8; jd++) {
        const int c = 8 * jd + 2 * ctg;
        *(float2*)(out0 + c) = make_float2(o[jd][0] * i0, o[jd][1] * i0);
        *(float2*)(out1 + c) = make_float2(o[jd][2] * i1, o[jd][3] * i1);
    }
}

// ---------------------------------------------------------------------------
extern "C" void kernel_launch(void* const* d_in, const int* in_sizes, int n_in,
                              void* d_out, int out_size) {
    const float* Q = (const float*)d_in[0];
    const float* K = (const float*)d_in[1];
    const float* V = (const float*)d_in[2];
    float* O = (float*)d_out;

    cudaFuncSetAttribute(flash_kernel, cudaFuncAttributeMaxDynamicSharedMemorySize, SM_TOTAL);

    prep_kernel<<<(N1 + N2 + 255) / 256, 256>>>(Q, K, V);

    dim3 grid(SEQ / BM, BH);
    flash_kernel<<<grid, 256, SM_TOTAL>>>(O);
}